// round 1
// baseline (speedup 1.0000x reference)
#include <cuda_runtime.h>
#include <cuda_bf16.h>
#include <mma.h>
#include <cstdint>

using namespace nvcuda;

// Problem constants (fixed by the reference: B=8, C=512, H=W=64, heads=8, d=64)
constexpr int BH = 64;          // B * num_heads
constexpr int D = 64;           // head_dim
constexpr int N = 4096;         // H*W
constexpr int SPLITS = 8;       // N-splits for the KV reduction
constexpr int NCHUNK = 64;      // columns per inner tile
constexpr int CHUNKS_PER_SPLIT = (N / SPLITS) / NCHUNK;  // 8
constexpr int LD = 72;          // padded smem leading dim (multiple of 8)

// Scratch (allocation-free contract -> __device__ globals)
__device__ float         g_kv_part[(size_t)BH * SPLITS * D * D];   // fp32 partial KVs
__device__ __nv_bfloat16 g_kv_hi[(size_t)BH * D * D];
__device__ __nv_bfloat16 g_kv_lo[(size_t)BH * D * D];

struct Smem {
    __nv_bfloat16 wf_hi[D * LD];
    __nv_bfloat16 wf_lo[D * LD];
    __nv_bfloat16 a_hi[D * LD];   // K/Q tile, then its feature-mapped version
    __nv_bfloat16 a_lo[D * LD];
    __nv_bfloat16 b_hi[D * LD];   // V tile (kernel A) / KV matrix (kernel B)
    __nv_bfloat16 b_lo[D * LD];
    float         f32[D * LD];    // fp32 staging for bias+relu
    float         bias[D];
};

typedef wmma::fragment<wmma::matrix_a, 16, 16, 16, __nv_bfloat16, wmma::row_major> FragA;
typedef wmma::fragment<wmma::matrix_a, 16, 16, 16, __nv_bfloat16, wmma::col_major> FragAc;
typedef wmma::fragment<wmma::matrix_b, 16, 16, 16, __nv_bfloat16, wmma::row_major> FragB;
typedef wmma::fragment<wmma::matrix_b, 16, 16, 16, __nv_bfloat16, wmma::col_major> FragBc;
typedef wmma::fragment<wmma::accumulator, 16, 16, 16, float> FragC;

__device__ __forceinline__ void split2(float x, __nv_bfloat16& hi, __nv_bfloat16& lo) {
    hi = __float2bfloat16(x);
    lo = __float2bfloat16(x - __bfloat162float(hi));
}

// Load a [64 x 64] fp32 tile (row stride gstride) from global, split into bf16 hi/lo in smem.
__device__ __forceinline__ void load_split_tile(const float* __restrict__ g, int gstride,
                                                __nv_bfloat16* hi, __nv_bfloat16* lo, int tid) {
    #pragma unroll
    for (int i = 0; i < (D * NCHUNK) / 128; i++) {
        int idx = tid + i * 128;
        int r = idx >> 6, c = idx & 63;
        float x = g[(size_t)r * gstride + c];
        __nv_bfloat16 h, l;
        split2(x, h, l);
        hi[r * LD + c] = h;
        lo[r * LD + c] = l;
    }
}

// In-place feature map on s->a_*:  a <- split(relu(Wf @ a + bias))
// wfh/wfl: this warp's 4 K-step fragments of rows [16*warp, 16*warp+16) of Wf.
__device__ __forceinline__ void feature_map(Smem* s, const FragA wfh[4], const FragA wfl[4],
                                            int warp, int tid) {
    #pragma unroll
    for (int nb = 0; nb < 4; nb++) {
        FragC acc;
        wmma::fill_fragment(acc, 0.0f);
        #pragma unroll
        for (int kk = 0; kk < 4; kk++) {
            FragB bh_, bl_;
            wmma::load_matrix_sync(bh_, s->a_hi + kk * 16 * LD + nb * 16, LD);
            wmma::load_matrix_sync(bl_, s->a_lo + kk * 16 * LD + nb * 16, LD);
            wmma::mma_sync(acc, wfh[kk], bh_, acc);
            wmma::mma_sync(acc, wfh[kk], bl_, acc);
            wmma::mma_sync(acc, wfl[kk], bh_, acc);
        }
        wmma::store_matrix_sync(s->f32 + warp * 16 * LD + nb * 16, acc, LD, wmma::mem_row_major);
    }
    __syncthreads();
    #pragma unroll
    for (int i = 0; i < (D * NCHUNK) / 128; i++) {
        int idx = tid + i * 128;
        int r = idx >> 6, c = idx & 63;
        float v = fmaxf(s->f32[r * LD + c] + s->bias[r], 0.0f);
        __nv_bfloat16 h, l;
        split2(v, h, l);
        s->a_hi[r * LD + c] = h;
        s->a_lo[r * LD + c] = l;
    }
    __syncthreads();
}

__device__ __forceinline__ void load_wf(Smem* s, const float* __restrict__ Wf,
                                        const float* __restrict__ bf, int tid) {
    #pragma unroll
    for (int i = 0; i < (D * D) / 128; i++) {
        int idx = tid + i * 128;
        int r = idx >> 6, c = idx & 63;
        __nv_bfloat16 h, l;
        split2(Wf[idx], h, l);
        s->wf_hi[r * LD + c] = h;
        s->wf_lo[r * LD + c] = l;
    }
    if (tid < D) s->bias[tid] = bf[tid];
    __syncthreads();
}

// ---------------- Kernel A: partial KV = relu(Wf K + b) @ V^T over an N-split ----------------
__global__ void __launch_bounds__(128) kernelA(const float* __restrict__ k,
                                               const float* __restrict__ v,
                                               const float* __restrict__ Wf,
                                               const float* __restrict__ bf) {
    extern __shared__ __align__(16) char smem_raw[];
    Smem* s = (Smem*)smem_raw;
    const int bh = blockIdx.y, split = blockIdx.x;
    const int tid = threadIdx.x, warp = tid >> 5;

    load_wf(s, Wf, bf, tid);

    FragA wfh[4], wfl[4];
    #pragma unroll
    for (int kk = 0; kk < 4; kk++) {
        wmma::load_matrix_sync(wfh[kk], s->wf_hi + warp * 16 * LD + kk * 16, LD);
        wmma::load_matrix_sync(wfl[kk], s->wf_lo + warp * 16 * LD + kk * 16, LD);
    }

    FragC kvacc[4];
    #pragma unroll
    for (int i = 0; i < 4; i++) wmma::fill_fragment(kvacc[i], 0.0f);

    const float* kbase = k + (size_t)bh * D * N;
    const float* vbase = v + (size_t)bh * D * N;
    const int n0 = split * (N / SPLITS);

    for (int sc = 0; sc < CHUNKS_PER_SPLIT; sc++) {
        const int noff = n0 + sc * NCHUNK;
        load_split_tile(kbase + noff, N, s->a_hi, s->a_lo, tid);
        load_split_tile(vbase + noff, N, s->b_hi, s->b_lo, tid);
        __syncthreads();

        feature_map(s, wfh, wfl, warp, tid);   // a <- relu(Wf K + b), split

        // KV[e,e2] += sum_n KF[e,n] * V[e2,n]   (A row-major, B col-major)
        #pragma unroll
        for (int kk = 0; kk < 4; kk++) {
            FragA ah, al;
            wmma::load_matrix_sync(ah, s->a_hi + warp * 16 * LD + kk * 16, LD);
            wmma::load_matrix_sync(al, s->a_lo + warp * 16 * LD + kk * 16, LD);
            #pragma unroll
            for (int nb = 0; nb < 4; nb++) {
                FragBc bh_, bl_;
                wmma::load_matrix_sync(bh_, s->b_hi + nb * 16 * LD + kk * 16, LD);
                wmma::load_matrix_sync(bl_, s->b_lo + nb * 16 * LD + kk * 16, LD);
                wmma::mma_sync(kvacc[nb], ah, bh_, kvacc[nb]);
                wmma::mma_sync(kvacc[nb], ah, bl_, kvacc[nb]);
                wmma::mma_sync(kvacc[nb], al, bh_, kvacc[nb]);
            }
        }
        __syncthreads();
    }

    float* part = g_kv_part + ((size_t)(bh * SPLITS + split)) * D * D;
    #pragma unroll
    for (int nb = 0; nb < 4; nb++)
        wmma::store_matrix_sync(part + warp * 16 * D + nb * 16, kvacc[nb], D, wmma::mem_row_major);
}

// ---------------- Kernel R: reduce partials, split KV to bf16 hi/lo ----------------
__global__ void __launch_bounds__(256) kernelR() {
    const int bh = blockIdx.x, tid = threadIdx.x;
    for (int idx = tid; idx < D * D; idx += 256) {
        float sum = 0.0f;
        #pragma unroll
        for (int sp = 0; sp < SPLITS; sp++)
            sum += g_kv_part[((size_t)(bh * SPLITS + sp)) * D * D + idx];
        __nv_bfloat16 h, l;
        split2(sum, h, l);
        g_kv_hi[(size_t)bh * D * D + idx] = h;
        g_kv_lo[(size_t)bh * D * D + idx] = l;
    }
}

// ---------------- Kernel B: Out = KV^T @ relu(Wf Q + b) ----------------
__global__ void __launch_bounds__(128) kernelB(const float* __restrict__ q,
                                               const float* __restrict__ Wf,
                                               const float* __restrict__ bf,
                                               float* __restrict__ out) {
    extern __shared__ __align__(16) char smem_raw[];
    Smem* s = (Smem*)smem_raw;
    const int bh = blockIdx.y, split = blockIdx.x;
    const int tid = threadIdx.x, warp = tid >> 5;

    load_wf(s, Wf, bf, tid);

    // KV matrix [d][e] row-major into b_hi/b_lo
    #pragma unroll
    for (int i = 0; i < (D * D) / 128; i++) {
        int idx = tid + i * 128;
        int r = idx >> 6, c = idx & 63;
        s->b_hi[r * LD + c] = g_kv_hi[(size_t)bh * D * D + idx];
        s->b_lo[r * LD + c] = g_kv_lo[(size_t)bh * D * D + idx];
    }
    __syncthreads();

    FragA wfh[4], wfl[4];
    #pragma unroll
    for (int kk = 0; kk < 4; kk++) {
        wmma::load_matrix_sync(wfh[kk], s->wf_hi + warp * 16 * LD + kk * 16, LD);
        wmma::load_matrix_sync(wfl[kk], s->wf_lo + warp * 16 * LD + kk * 16, LD);
    }

    const float* qbase = q + (size_t)bh * D * N;
    float* obase = out + (size_t)bh * D * N;
    const int n0 = split * (N / SPLITS);

    for (int sc = 0; sc < CHUNKS_PER_SPLIT; sc++) {
        const int noff = n0 + sc * NCHUNK;
        load_split_tile(qbase + noff, N, s->a_hi, s->a_lo, tid);
        __syncthreads();

        feature_map(s, wfh, wfl, warp, tid);   // a <- relu(Wf Q + b), split

        // Out[e_out, n] = sum_d KV[d, e_out] * QF[d, n]
        // A = KV as col-major (rows e_out = this warp's block), B = QF row-major.
        FragAc kah[4], kal[4];
        #pragma unroll
        for (int kk = 0; kk < 4; kk++) {
            wmma::load_matrix_sync(kah[kk], s->b_hi + kk * 16 * LD + warp * 16, LD);
            wmma::load_matrix_sync(kal[kk], s->b_lo + kk * 16 * LD + warp * 16, LD);
        }
        #pragma unroll
        for (int nb = 0; nb < 4; nb++) {
            FragC acc;
            wmma::fill_fragment(acc, 0.0f);
            #pragma unroll
            for (int kk = 0; kk < 4; kk++) {
                FragB qh, ql;
                wmma::load_matrix_sync(qh, s->a_hi + kk * 16 * LD + nb * 16, LD);
                wmma::load_matrix_sync(ql, s->a_lo + kk * 16 * LD + nb * 16, LD);
                wmma::mma_sync(acc, kah[kk], qh, acc);
                wmma::mma_sync(acc, kah[kk], ql, acc);
                wmma::mma_sync(acc, kal[kk], qh, acc);
            }
            wmma::store_matrix_sync(obase + (size_t)(warp * 16) * N + noff + nb * 16,
                                    acc, N, wmma::mem_row_major);
        }
        __syncthreads();
    }
}

extern "C" void kernel_launch(void* const* d_in, const int* in_sizes, int n_in,
                              void* d_out, int out_size) {
    const float* q  = (const float*)d_in[0];
    const float* k  = (const float*)d_in[1];
    const float* v  = (const float*)d_in[2];
    const float* Wf = (const float*)d_in[3];
    const float* bf = (const float*)d_in[4];
    float* out = (float*)d_out;

    const int smem = (int)sizeof(Smem);
    cudaFuncSetAttribute(kernelA, cudaFuncAttributeMaxDynamicSharedMemorySize, smem);
    cudaFuncSetAttribute(kernelB, cudaFuncAttributeMaxDynamicSharedMemorySize, smem);

    kernelA<<<dim3(SPLITS, BH), 128, smem>>>(k, v, Wf, bf);
    kernelR<<<BH, 256>>>();
    kernelB<<<dim3(SPLITS, BH), 128, smem>>>(q, Wf, bf, out);
}

// round 2
// speedup vs baseline: 1.2658x; 1.2658x over previous
#include <cuda_runtime.h>
#include <cuda_bf16.h>
#include <mma.h>
#include <cstdint>

using namespace nvcuda;

constexpr int BH = 64;          // B * num_heads
constexpr int D = 64;           // head_dim
constexpr int N = 4096;         // H*W
constexpr int SPLITS = 8;       // N-splits for the KV reduction
constexpr int NCHUNK = 64;      // columns per inner tile
constexpr int CPS = (N / SPLITS) / NCHUNK;  // 8 chunks per split
constexpr int LD = 72;          // padded smem leading dim

__device__ float         g_kv_part[(size_t)BH * SPLITS * D * D];
__device__ __nv_bfloat16 g_kv_hi[(size_t)BH * D * D];
__device__ __nv_bfloat16 g_kv_lo[(size_t)BH * D * D];

struct Smem {
    __nv_bfloat16 wf_hi[D * LD];
    __nv_bfloat16 wf_lo[D * LD];
    __nv_bfloat16 a_hi[D * LD];   // K/Q tile -> feature-mapped tile
    __nv_bfloat16 a_lo[D * LD];
    __nv_bfloat16 b_hi[D * LD];   // V tile (A) / KV matrix (B)
    __nv_bfloat16 b_lo[D * LD];
    float         f32[D * LD];    // fp32 staging for bias+relu
    float         bias[D];
};

typedef wmma::fragment<wmma::matrix_a, 16, 16, 16, __nv_bfloat16, wmma::row_major> FragA;
typedef wmma::fragment<wmma::matrix_a, 16, 16, 16, __nv_bfloat16, wmma::col_major> FragAc;
typedef wmma::fragment<wmma::matrix_b, 16, 16, 16, __nv_bfloat16, wmma::row_major> FragB;
typedef wmma::fragment<wmma::matrix_b, 16, 16, 16, __nv_bfloat16, wmma::col_major> FragBc;
typedef wmma::fragment<wmma::accumulator, 16, 16, 16, float> FragC;

__device__ __forceinline__ void split2(float x, __nv_bfloat16& hi, __nv_bfloat16& lo) {
    hi = __float2bfloat16(x);
    lo = __float2bfloat16(x - __bfloat162float(hi));
}

// Store one float4 as 4 bf16 hi + 4 bf16 lo (two 4B stores each).
__device__ __forceinline__ void split_store4(float4 x, __nv_bfloat16* hi, __nv_bfloat16* lo) {
    float v[4] = {x.x, x.y, x.z, x.w};
    __nv_bfloat16 h[4], l[4];
    #pragma unroll
    for (int j = 0; j < 4; j++) split2(v[j], h[j], l[j]);
    ((__nv_bfloat162*)hi)[0] = __halves2bfloat162(h[0], h[1]);
    ((__nv_bfloat162*)hi)[1] = __halves2bfloat162(h[2], h[3]);
    ((__nv_bfloat162*)lo)[0] = __halves2bfloat162(l[0], l[1]);
    ((__nv_bfloat162*)lo)[1] = __halves2bfloat162(l[2], l[3]);
}

// Prefetch one 64x64 fp32 tile as 4 float4 per thread (256 threads).
__device__ __forceinline__ void tile_ld(const float* __restrict__ g, int tid, float4 r[4]) {
    #pragma unroll
    for (int i = 0; i < 4; i++) {
        int idx4 = tid + i * 256;
        int row = idx4 >> 4, c4 = idx4 & 15;
        r[i] = *(const float4*)(g + (size_t)row * N + c4 * 4);
    }
}

__device__ __forceinline__ void tile_st(const float4 r[4], __nv_bfloat16* hi, __nv_bfloat16* lo, int tid) {
    #pragma unroll
    for (int i = 0; i < 4; i++) {
        int idx4 = tid + i * 256;
        int row = idx4 >> 4, c = (idx4 & 15) * 4;
        split_store4(r[i], hi + row * LD + c, lo + row * LD + c);
    }
}

__device__ __forceinline__ void load_wf(Smem* s, const float* __restrict__ Wf,
                                        const float* __restrict__ bf, int tid) {
    #pragma unroll
    for (int i = 0; i < (D * D) / 256; i++) {
        int idx = tid + i * 256;
        int r = idx >> 6, c = idx & 63;
        __nv_bfloat16 h, l;
        split2(Wf[idx], h, l);
        s->wf_hi[r * LD + c] = h;
        s->wf_lo[r * LD + c] = l;
    }
    if (tid < D) s->bias[tid] = bf[tid];
}

// Feature map MMA phase: warp (rb, cp) computes f32[rb block][cb blocks 2cp,2cp+1].
__device__ __forceinline__ void fmap_mma(Smem* s, const FragA wfh[4], const FragA wfl[4],
                                         int rb, int cp) {
    #pragma unroll
    for (int c = 0; c < 2; c++) {
        int cb = 2 * cp + c;
        FragC acc;
        wmma::fill_fragment(acc, 0.0f);
        #pragma unroll
        for (int kk = 0; kk < 4; kk++) {
            FragB bh_, bl_;
            wmma::load_matrix_sync(bh_, s->a_hi + kk * 16 * LD + cb * 16, LD);
            wmma::load_matrix_sync(bl_, s->a_lo + kk * 16 * LD + cb * 16, LD);
            wmma::mma_sync(acc, wfh[kk], bh_, acc);
            wmma::mma_sync(acc, wfh[kk], bl_, acc);
            wmma::mma_sync(acc, wfl[kk], bh_, acc);
        }
        wmma::store_matrix_sync(s->f32 + rb * 16 * LD + cb * 16, acc, LD, wmma::mem_row_major);
    }
}

// Relu + bias + split back into a_hi/a_lo (256 threads).
__device__ __forceinline__ void relu_split(Smem* s, int tid) {
    #pragma unroll
    for (int i = 0; i < (D * NCHUNK) / 256; i++) {
        int idx = tid + i * 256;
        int r = idx >> 6, c = idx & 63;
        float v = fmaxf(s->f32[r * LD + c] + s->bias[r], 0.0f);
        __nv_bfloat16 h, l;
        split2(v, h, l);
        s->a_hi[r * LD + c] = h;
        s->a_lo[r * LD + c] = l;
    }
}

// ---------------- Kernel A: partial KV = relu(Wf K + b) @ V^T over an N-split ----------------
__global__ void __launch_bounds__(256, 2) kernelA(const float* __restrict__ k,
                                                  const float* __restrict__ v,
                                                  const float* __restrict__ Wf,
                                                  const float* __restrict__ bf) {
    extern __shared__ __align__(16) char smem_raw[];
    Smem* s = (Smem*)smem_raw;
    const int bh = blockIdx.y, split = blockIdx.x;
    const int tid = threadIdx.x, warp = tid >> 5;
    const int rb = warp >> 1, cp = warp & 1;

    load_wf(s, Wf, bf, tid);
    __syncthreads();

    FragA wfh[4], wfl[4];
    #pragma unroll
    for (int kk = 0; kk < 4; kk++) {
        wmma::load_matrix_sync(wfh[kk], s->wf_hi + rb * 16 * LD + kk * 16, LD);
        wmma::load_matrix_sync(wfl[kk], s->wf_lo + rb * 16 * LD + kk * 16, LD);
    }

    FragC kvacc[2];
    wmma::fill_fragment(kvacc[0], 0.0f);
    wmma::fill_fragment(kvacc[1], 0.0f);

    const float* kbase = k + (size_t)bh * D * N + split * (N / SPLITS);
    const float* vbase = v + (size_t)bh * D * N + split * (N / SPLITS);

    float4 kreg[4], vreg[4];
    tile_ld(kbase, tid, kreg);
    tile_ld(vbase, tid, vreg);

    for (int sc = 0; sc < CPS; sc++) {
        tile_st(kreg, s->a_hi, s->a_lo, tid);
        tile_st(vreg, s->b_hi, s->b_lo, tid);
        __syncthreads();

        if (sc + 1 < CPS) {                      // prefetch next chunk during MMAs
            tile_ld(kbase + (sc + 1) * NCHUNK, tid, kreg);
            tile_ld(vbase + (sc + 1) * NCHUNK, tid, vreg);
        }

        fmap_mma(s, wfh, wfl, rb, cp);           // f32 <- Wf @ K
        __syncthreads();
        relu_split(s, tid);                      // a <- split(relu(f32 + b))
        __syncthreads();

        // KV[e,e2] += KF[e,:] V[e2,:]^T
        #pragma unroll
        for (int kk = 0; kk < 4; kk++) {
            FragA ah, al;
            wmma::load_matrix_sync(ah, s->a_hi + rb * 16 * LD + kk * 16, LD);
            wmma::load_matrix_sync(al, s->a_lo + rb * 16 * LD + kk * 16, LD);
            #pragma unroll
            for (int c = 0; c < 2; c++) {
                int cb = 2 * cp + c;
                FragBc bh_, bl_;
                wmma::load_matrix_sync(bh_, s->b_hi + cb * 16 * LD + kk * 16, LD);
                wmma::load_matrix_sync(bl_, s->b_lo + cb * 16 * LD + kk * 16, LD);
                wmma::mma_sync(kvacc[c], ah, bh_, kvacc[c]);
                wmma::mma_sync(kvacc[c], ah, bl_, kvacc[c]);
                wmma::mma_sync(kvacc[c], al, bh_, kvacc[c]);
            }
        }
        __syncthreads();
    }

    float* part = g_kv_part + ((size_t)(bh * SPLITS + split)) * D * D;
    #pragma unroll
    for (int c = 0; c < 2; c++)
        wmma::store_matrix_sync(part + rb * 16 * D + (2 * cp + c) * 16, kvacc[c], D,
                                wmma::mem_row_major);
}

// ---------------- Kernel R: reduce partials, split KV to bf16 hi/lo ----------------
__global__ void __launch_bounds__(256) kernelR() {
    const int bh = blockIdx.x, tid = threadIdx.x;
    for (int idx = tid; idx < D * D; idx += 256) {
        float sum = 0.0f;
        #pragma unroll
        for (int sp = 0; sp < SPLITS; sp++)
            sum += g_kv_part[((size_t)(bh * SPLITS + sp)) * D * D + idx];
        __nv_bfloat16 h, l;
        split2(sum, h, l);
        g_kv_hi[(size_t)bh * D * D + idx] = h;
        g_kv_lo[(size_t)bh * D * D + idx] = l;
    }
}

// ---------------- Kernel B: Out = KV^T @ relu(Wf Q + b) ----------------
__global__ void __launch_bounds__(256, 2) kernelB(const float* __restrict__ q,
                                                  const float* __restrict__ Wf,
                                                  const float* __restrict__ bf,
                                                  float* __restrict__ out) {
    extern __shared__ __align__(16) char smem_raw[];
    Smem* s = (Smem*)smem_raw;
    const int bh = blockIdx.y, split = blockIdx.x;
    const int tid = threadIdx.x, warp = tid >> 5;
    const int rb = warp >> 1, cp = warp & 1;

    load_wf(s, Wf, bf, tid);
    // KV [d][e] row-major into b_hi/b_lo
    #pragma unroll
    for (int i = 0; i < (D * D) / 256; i++) {
        int idx = tid + i * 256;
        int r = idx >> 6, c = idx & 63;
        s->b_hi[r * LD + c] = g_kv_hi[(size_t)bh * D * D + idx];
        s->b_lo[r * LD + c] = g_kv_lo[(size_t)bh * D * D + idx];
    }
    __syncthreads();

    FragA wfh[4], wfl[4];
    FragAc kah[4], kal[4];
    #pragma unroll
    for (int kk = 0; kk < 4; kk++) {
        wmma::load_matrix_sync(wfh[kk], s->wf_hi + rb * 16 * LD + kk * 16, LD);
        wmma::load_matrix_sync(wfl[kk], s->wf_lo + rb * 16 * LD + kk * 16, LD);
        wmma::load_matrix_sync(kah[kk], s->b_hi + kk * 16 * LD + rb * 16, LD);   // KV col-major
        wmma::load_matrix_sync(kal[kk], s->b_lo + kk * 16 * LD + rb * 16, LD);
    }

    const float* qbase = q + (size_t)bh * D * N + split * (N / SPLITS);
    float* obase = out + (size_t)bh * D * N + split * (N / SPLITS);

    float4 qreg[4];
    tile_ld(qbase, tid, qreg);

    for (int sc = 0; sc < CPS; sc++) {
        tile_st(qreg, s->a_hi, s->a_lo, tid);
        __syncthreads();

        if (sc + 1 < CPS) tile_ld(qbase + (sc + 1) * NCHUNK, tid, qreg);

        fmap_mma(s, wfh, wfl, rb, cp);
        __syncthreads();
        relu_split(s, tid);
        __syncthreads();

        // Out[e2, n] = sum_d KV[d, e2] QF[d, n]
        #pragma unroll
        for (int c = 0; c < 2; c++) {
            int cb = 2 * cp + c;
            FragC acc;
            wmma::fill_fragment(acc, 0.0f);
            #pragma unroll
            for (int kk = 0; kk < 4; kk++) {
                FragB qh, ql;
                wmma::load_matrix_sync(qh, s->a_hi + kk * 16 * LD + cb * 16, LD);
                wmma::load_matrix_sync(ql, s->a_lo + kk * 16 * LD + cb * 16, LD);
                wmma::mma_sync(acc, kah[kk], qh, acc);
                wmma::mma_sync(acc, kah[kk], ql, acc);
                wmma::mma_sync(acc, kal[kk], qh, acc);
            }
            wmma::store_matrix_sync(obase + (size_t)(rb * 16) * N + sc * NCHUNK + cb * 16,
                                    acc, N, wmma::mem_row_major);
        }
        __syncthreads();
    }
}

extern "C" void kernel_launch(void* const* d_in, const int* in_sizes, int n_in,
                              void* d_out, int out_size) {
    const float* q  = (const float*)d_in[0];
    const float* k  = (const float*)d_in[1];
    const float* v  = (const float*)d_in[2];
    const float* Wf = (const float*)d_in[3];
    const float* bf = (const float*)d_in[4];
    float* out = (float*)d_out;

    const int smem = (int)sizeof(Smem);
    cudaFuncSetAttribute(kernelA, cudaFuncAttributeMaxDynamicSharedMemorySize, smem);
    cudaFuncSetAttribute(kernelB, cudaFuncAttributeMaxDynamicSharedMemorySize, smem);

    kernelA<<<dim3(SPLITS, BH), 256, smem>>>(k, v, Wf, bf);
    kernelR<<<BH, 256>>>();
    kernelB<<<dim3(SPLITS, BH), 256, smem>>>(q, Wf, bf, out);
}

// round 3
// speedup vs baseline: 1.9508x; 1.5412x over previous
#include <cuda_runtime.h>
#include <cuda_bf16.h>
#include <cstdint>

constexpr int BH = 64, D = 64, N = 4096;
constexpr int SPLITS = 4;
constexpr int NSEG = N / SPLITS;        // 1024
constexpr int CPS_A = NSEG / 64;        // 16 chunks of 64 cols
constexpr int CPS_B = NSEG / 128;       // 8 chunks of 128 cols

__device__ float         g_kv_part[(size_t)BH * SPLITS * D * D];
__device__ __nv_bfloat16 g_kvt_hi[(size_t)BH * D * D];   // KV^T [e2][e]
__device__ __nv_bfloat16 g_kvt_lo[(size_t)BH * D * D];

// ---- kernelA smem byte offsets (LD 72 bf16 = 144B rows) ----
constexpr int LDA = 144;
constexpr int A_KH = 0, A_KL = 9216, A_VH = 18432, A_VL = 27648;
constexpr int A_WFH = 36864, A_WFL = 46080, A_BIAS = 55296, A_KVRED = 55552;
constexpr int A_SMEM = A_KVRED + 2 * 64 * 64 * 4;        // 88320
// ---- kernelB smem (q: LD 136 bf16 = 272B; out: LD 132 fp32) ----
constexpr int LDQ = 272, LDO = 132;
constexpr int B_QH = 0, B_QL = 17408, B_OUT = 0;         // OUT aliases QH/QL
constexpr int B_WFH = 34816, B_WFL = 44032, B_KVTH = 53248, B_KVTL = 62464, B_BIAS = 71680;
constexpr int B_SMEM = 71936;

// ---------------- PTX helpers ----------------
__device__ __forceinline__ void ldsm4(uint32_t r[4], uint32_t a) {
    asm volatile("ldmatrix.sync.aligned.m8n8.x4.shared.b16 {%0,%1,%2,%3},[%4];"
                 : "=r"(r[0]), "=r"(r[1]), "=r"(r[2]), "=r"(r[3]) : "r"(a));
}
__device__ __forceinline__ void ldsm4t(uint32_t r[4], uint32_t a) {
    asm volatile("ldmatrix.sync.aligned.m8n8.x4.trans.shared.b16 {%0,%1,%2,%3},[%4];"
                 : "=r"(r[0]), "=r"(r[1]), "=r"(r[2]), "=r"(r[3]) : "r"(a));
}
__device__ __forceinline__ void mma_bf16(float c[4], const uint32_t a[4], const uint32_t b[2]) {
    asm volatile("mma.sync.aligned.m16n8k16.row.col.f32.bf16.bf16.f32 "
                 "{%0,%1,%2,%3},{%4,%5,%6,%7},{%8,%9},{%0,%1,%2,%3};"
                 : "+f"(c[0]), "+f"(c[1]), "+f"(c[2]), "+f"(c[3])
                 : "r"(a[0]), "r"(a[1]), "r"(a[2]), "r"(a[3]), "r"(b[0]), "r"(b[1]));
}
// A-pattern ldmatrix addresses: lanes 0-15 -> rows r0+(l&15) @ c0 ; 16-31 -> @ c0+8
__device__ __forceinline__ uint32_t patA(uint32_t base, int ldB, int r0, int c0, int lane) {
    return base + (uint32_t)((r0 + (lane & 15)) * ldB + (c0 + ((lane >> 4) << 3)) * 2);
}
// B-pattern: g0 rows r0..7 @ c0 ; g1 rows r0..7 @ c0+8 ; g2 rows r0+8..15 @ c0 ; g3 @ c0+8
__device__ __forceinline__ uint32_t patB(uint32_t base, int ldB, int r0, int c0, int lane) {
    return base + (uint32_t)((r0 + (lane & 7) + ((lane >> 4) << 3)) * ldB
                             + (c0 + (((lane >> 3) & 1) << 3)) * 2);
}
__device__ __forceinline__ void split2(float x, __nv_bfloat16& hi, __nv_bfloat16& lo) {
    hi = __float2bfloat16(x);
    lo = __float2bfloat16(x - __bfloat162float(hi));
}
// pack (x0,x1) -> bf16x2 hi reg + bf16x2 lo reg (x0 in low half)
__device__ __forceinline__ void split_pack(float x0, float x1, uint32_t& hi, uint32_t& lo) {
    __nv_bfloat16 h0 = __float2bfloat16(x0), h1 = __float2bfloat16(x1);
    float r0 = x0 - __bfloat162float(h0), r1 = x1 - __bfloat162float(h1);
    __nv_bfloat162 hp = __halves2bfloat162(h0, h1);
    __nv_bfloat162 lp = __halves2bfloat162(__float2bfloat16(r0), __float2bfloat16(r1));
    hi = *(uint32_t*)&hp;
    lo = *(uint32_t*)&lp;
}
__device__ __forceinline__ void split_store4(float4 x, __nv_bfloat16* hi, __nv_bfloat16* lo) {
    uint32_t h, l;
    split_pack(x.x, x.y, h, l);
    ((uint32_t*)hi)[0] = h; ((uint32_t*)lo)[0] = l;
    split_pack(x.z, x.w, h, l);
    ((uint32_t*)hi)[1] = h; ((uint32_t*)lo)[1] = l;
}

// 64-col fp32 tile: gmem -> 4 float4/thread (256 thr)
__device__ __forceinline__ void ld_tile64(const float* __restrict__ g, int tid, float4 r[4]) {
    #pragma unroll
    for (int i = 0; i < 4; i++) {
        int idx4 = tid + i * 256;
        r[i] = *(const float4*)(g + (size_t)(idx4 >> 4) * N + (idx4 & 15) * 4);
    }
}
__device__ __forceinline__ void st_tile64(char* sm, int offH, int offL, const float4 r[4], int tid) {
    #pragma unroll
    for (int i = 0; i < 4; i++) {
        int idx4 = tid + i * 256;
        int row = idx4 >> 4, c = (idx4 & 15) * 4;
        split_store4(r[i], (__nv_bfloat16*)(sm + offH) + row * 72 + c,
                           (__nv_bfloat16*)(sm + offL) + row * 72 + c);
    }
}
// 128-col tile: 8 float4/thread
__device__ __forceinline__ void ld_tile128(const float* __restrict__ g, int tid, float4 r[8]) {
    #pragma unroll
    for (int i = 0; i < 8; i++) {
        int idx4 = tid + i * 256;
        r[i] = *(const float4*)(g + (size_t)(idx4 >> 5) * N + (idx4 & 31) * 4);
    }
}
__device__ __forceinline__ void st_tile128(char* sm, int offH, int offL, const float4 r[8], int tid) {
    #pragma unroll
    for (int i = 0; i < 8; i++) {
        int idx4 = tid + i * 256;
        int row = idx4 >> 5, c = (idx4 & 31) * 4;
        split_store4(r[i], (__nv_bfloat16*)(sm + offH) + row * 136 + c,
                           (__nv_bfloat16*)(sm + offL) + row * 136 + c);
    }
}

__device__ __forceinline__ void load_wf_split(char* sm, int offH, int offL, int offBias,
                                              const float* __restrict__ Wf,
                                              const float* __restrict__ bf, int tid) {
    #pragma unroll
    for (int i = 0; i < 16; i++) {
        int idx = tid + i * 256;
        int r = idx >> 6, c = idx & 63;
        __nv_bfloat16 h, l;
        split2(Wf[idx], h, l);
        ((__nv_bfloat16*)(sm + offH))[r * 72 + c] = h;
        ((__nv_bfloat16*)(sm + offL))[r * 72 + c] = l;
    }
    if (tid < 64) ((float*)(sm + offBias))[tid] = bf[tid];
}

// ============ Kernel A: KV partial = relu(Wf K + b) @ V^T over one N-segment ============
__global__ void __launch_bounds__(256, 2) kernelA(const float* __restrict__ k,
                                                  const float* __restrict__ v,
                                                  const float* __restrict__ Wf,
                                                  const float* __restrict__ bf) {
    extern __shared__ __align__(16) char sm[];
    const uint32_t sm32 = (uint32_t)__cvta_generic_to_shared(sm);
    const int bh = blockIdx.y, split = blockIdx.x;
    const int tid = threadIdx.x, lane = tid & 31, warp = tid >> 5;
    const int rb = warp >> 1, nh = warp & 1;

    load_wf_split(sm, A_WFH, A_WFL, A_BIAS, Wf, bf, tid);
    __syncthreads();

    const float bias_r0 = ((float*)(sm + A_BIAS))[rb * 16 + (lane >> 2)];
    const float bias_r1 = ((float*)(sm + A_BIAS))[rb * 16 + (lane >> 2) + 8];

    float kvacc[8][4];
    #pragma unroll
    for (int g = 0; g < 8; g++)
        #pragma unroll
        for (int j = 0; j < 4; j++) kvacc[g][j] = 0.0f;

    const float* kbase = k + (size_t)bh * D * N + split * NSEG;
    const float* vbase = v + (size_t)bh * D * N + split * NSEG;

    float4 kreg[4], vreg[4];
    ld_tile64(kbase, tid, kreg);
    ld_tile64(vbase, tid, vreg);

    for (int sc = 0; sc < CPS_A; sc++) {
        st_tile64(sm, A_KH, A_KL, kreg, tid);
        st_tile64(sm, A_VH, A_VL, vreg, tid);
        __syncthreads();
        if (sc + 1 < CPS_A) {
            ld_tile64(kbase + (sc + 1) * 64, tid, kreg);
            ld_tile64(vbase + (sc + 1) * 64, tid, vreg);
        }

        // ---- feature map: C[rb rows 16, nh-half 32] in registers ----
        float c[2][2][4];
        #pragma unroll
        for (int t = 0; t < 2; t++)
            #pragma unroll
            for (int g = 0; g < 2; g++)
                #pragma unroll
                for (int j = 0; j < 4; j++) c[t][g][j] = 0.0f;

        #pragma unroll
        for (int kk = 0; kk < 4; kk++) {
            uint32_t wh[4], wl[4];
            ldsm4(wh, patA(sm32 + A_WFH, LDA, rb * 16, kk * 16, lane));
            ldsm4(wl, patA(sm32 + A_WFL, LDA, rb * 16, kk * 16, lane));
            #pragma unroll
            for (int t = 0; t < 2; t++) {
                const int n0 = nh * 32 + t * 16;
                uint32_t bh4[4], bl4[4];
                ldsm4t(bh4, patA(sm32 + A_KH, LDA, kk * 16, n0, lane));
                ldsm4t(bl4, patA(sm32 + A_KL, LDA, kk * 16, n0, lane));
                mma_bf16(c[t][0], wh, bh4);     mma_bf16(c[t][0], wh, bl4);
                mma_bf16(c[t][0], wl, bh4);
                mma_bf16(c[t][1], wh, bh4 + 2); mma_bf16(c[t][1], wh, bl4 + 2);
                mma_bf16(c[t][1], wl, bh4 + 2);
            }
        }

        // ---- bias + relu + split, chain into A fragments ----
        uint32_t ah[2][4], al[2][4];
        #pragma unroll
        for (int t = 0; t < 2; t++) {
            float v00 = fmaxf(c[t][0][0] + bias_r0, 0.f), v01 = fmaxf(c[t][0][1] + bias_r0, 0.f);
            float v02 = fmaxf(c[t][0][2] + bias_r1, 0.f), v03 = fmaxf(c[t][0][3] + bias_r1, 0.f);
            float v10 = fmaxf(c[t][1][0] + bias_r0, 0.f), v11 = fmaxf(c[t][1][1] + bias_r0, 0.f);
            float v12 = fmaxf(c[t][1][2] + bias_r1, 0.f), v13 = fmaxf(c[t][1][3] + bias_r1, 0.f);
            split_pack(v00, v01, ah[t][0], al[t][0]);
            split_pack(v02, v03, ah[t][1], al[t][1]);
            split_pack(v10, v11, ah[t][2], al[t][2]);
            split_pack(v12, v13, ah[t][3], al[t][3]);
        }

        // ---- KV += fmapK @ V^T (k-dim = n, two 16-steps) ----
        #pragma unroll
        for (int g4 = 0; g4 < 4; g4++) {
            #pragma unroll
            for (int t = 0; t < 2; t++) {
                const int n0 = nh * 32 + t * 16;
                uint32_t vh4[4], vl4[4];
                ldsm4(vh4, patB(sm32 + A_VH, LDA, g4 * 16, n0, lane));
                ldsm4(vl4, patB(sm32 + A_VL, LDA, g4 * 16, n0, lane));
                mma_bf16(kvacc[2 * g4], ah[t], vh4);     mma_bf16(kvacc[2 * g4], ah[t], vl4);
                mma_bf16(kvacc[2 * g4], al[t], vh4);
                mma_bf16(kvacc[2 * g4 + 1], ah[t], vh4 + 2); mma_bf16(kvacc[2 * g4 + 1], ah[t], vl4 + 2);
                mma_bf16(kvacc[2 * g4 + 1], al[t], vh4 + 2);
            }
        }
        __syncthreads();
    }

    // ---- combine nh halves, write partial KV ----
    float* kvred = (float*)(sm + A_KVRED);
    #pragma unroll
    for (int g = 0; g < 8; g++) {
        int col = g * 8 + 2 * (lane & 3);
        int row = rb * 16 + (lane >> 2);
        float* dst = kvred + nh * 4096;
        dst[row * 64 + col]           = kvacc[g][0];
        dst[row * 64 + col + 1]       = kvacc[g][1];
        dst[(row + 8) * 64 + col]     = kvacc[g][2];
        dst[(row + 8) * 64 + col + 1] = kvacc[g][3];
    }
    __syncthreads();
    float* part = g_kv_part + ((size_t)(bh * SPLITS + split)) * 4096;
    for (int idx = tid; idx < 4096; idx += 256)
        part[idx] = kvred[idx] + kvred[4096 + idx];
}

// ============ Kernel R: reduce partials, store KV^T as bf16 hi/lo ============
__global__ void __launch_bounds__(256) kernelR() {
    const int bh = blockIdx.x, tid = threadIdx.x;
    const float* base = g_kv_part + (size_t)bh * SPLITS * 4096;
    for (int idx = tid; idx < 4096; idx += 256) {
        float s = base[idx] + base[4096 + idx] + base[8192 + idx] + base[12288 + idx];
        int e = idx >> 6, e2 = idx & 63;
        __nv_bfloat16 h, l;
        split2(s, h, l);
        g_kvt_hi[(size_t)bh * 4096 + e2 * 64 + e] = h;
        g_kvt_lo[(size_t)bh * 4096 + e2 * 64 + e] = l;
    }
}

// ============ Kernel B: Out^T[n,e2] = fmapQ'[n,:] @ KV ============
__global__ void __launch_bounds__(256, 2) kernelB(const float* __restrict__ q,
                                                  const float* __restrict__ Wf,
                                                  const float* __restrict__ bf,
                                                  float* __restrict__ out) {
    extern __shared__ __align__(16) char sm[];
    const uint32_t sm32 = (uint32_t)__cvta_generic_to_shared(sm);
    const int bh = blockIdx.y, split = blockIdx.x;
    const int tid = threadIdx.x, lane = tid & 31, warp = tid >> 5;
    const int n0w = warp * 16;

    load_wf_split(sm, B_WFH, B_WFL, B_BIAS, Wf, bf, tid);
    {   // KV^T tiles
        __nv_bfloat16* kh = (__nv_bfloat16*)(sm + B_KVTH);
        __nv_bfloat16* kl = (__nv_bfloat16*)(sm + B_KVTL);
        #pragma unroll
        for (int i = 0; i < 16; i++) {
            int idx = tid + i * 256;
            int r = idx >> 6, c = idx & 63;
            kh[r * 72 + c] = g_kvt_hi[(size_t)bh * 4096 + idx];
            kl[r * 72 + c] = g_kvt_lo[(size_t)bh * 4096 + idx];
        }
    }
    __syncthreads();

    const float* bias_s = (const float*)(sm + B_BIAS);
    const float* qbase = q + (size_t)bh * D * N + split * NSEG;
    float* obase = out + (size_t)bh * D * N + split * NSEG;

    float4 qreg[8];
    ld_tile128(qbase, tid, qreg);

    for (int sc = 0; sc < CPS_B; sc++) {
        st_tile128(sm, B_QH, B_QL, qreg, tid);
        __syncthreads();

        // ---- fmap': C3[n rows 16 (this warp), e 64] ----
        float c3[8][4];
        #pragma unroll
        for (int g = 0; g < 8; g++)
            #pragma unroll
            for (int j = 0; j < 4; j++) c3[g][j] = 0.0f;

        #pragma unroll
        for (int kk = 0; kk < 4; kk++) {
            uint32_t aQh[4], aQl[4];
            ldsm4t(aQh, patB(sm32 + B_QH, LDQ, kk * 16, n0w, lane));
            ldsm4t(aQl, patB(sm32 + B_QL, LDQ, kk * 16, n0w, lane));
            #pragma unroll
            for (int g4 = 0; g4 < 4; g4++) {
                uint32_t wbh[4], wbl[4];
                ldsm4(wbh, patB(sm32 + B_WFH, LDA, g4 * 16, kk * 16, lane));
                ldsm4(wbl, patB(sm32 + B_WFL, LDA, g4 * 16, kk * 16, lane));
                mma_bf16(c3[2 * g4], aQh, wbh);     mma_bf16(c3[2 * g4], aQh, wbl);
                mma_bf16(c3[2 * g4], aQl, wbh);
                mma_bf16(c3[2 * g4 + 1], aQh, wbh + 2); mma_bf16(c3[2 * g4 + 1], aQh, wbl + 2);
                mma_bf16(c3[2 * g4 + 1], aQl, wbh + 2);
            }
        }
        __syncthreads();   // q reads done (outbuf aliases q region)

        // ---- Out mma: reduce over e in 4 k-steps, chained A from c3 ----
        float oacc[8][4];
        #pragma unroll
        for (int g = 0; g < 8; g++)
            #pragma unroll
            for (int j = 0; j < 4; j++) oacc[g][j] = 0.0f;

        #pragma unroll
        for (int ks = 0; ks < 4; ks++) {
            const int g0 = 2 * ks, g1 = 2 * ks + 1;
            float b00 = bias_s[g0 * 8 + 2 * (lane & 3)], b01 = bias_s[g0 * 8 + 2 * (lane & 3) + 1];
            float b10 = bias_s[g1 * 8 + 2 * (lane & 3)], b11 = bias_s[g1 * 8 + 2 * (lane & 3) + 1];
            float v00 = fmaxf(c3[g0][0] + b00, 0.f), v01 = fmaxf(c3[g0][1] + b01, 0.f);
            float v02 = fmaxf(c3[g0][2] + b00, 0.f), v03 = fmaxf(c3[g0][3] + b01, 0.f);
            float v10 = fmaxf(c3[g1][0] + b10, 0.f), v11 = fmaxf(c3[g1][1] + b11, 0.f);
            float v12 = fmaxf(c3[g1][2] + b10, 0.f), v13 = fmaxf(c3[g1][3] + b11, 0.f);
            uint32_t a4h[4], a4l[4];
            split_pack(v00, v01, a4h[0], a4l[0]);
            split_pack(v02, v03, a4h[1], a4l[1]);
            split_pack(v10, v11, a4h[2], a4l[2]);
            split_pack(v12, v13, a4h[3], a4l[3]);

            #pragma unroll
            for (int g4 = 0; g4 < 4; g4++) {
                uint32_t kbh[4], kbl[4];
                ldsm4(kbh, patB(sm32 + B_KVTH, LDA, g4 * 16, ks * 16, lane));
                ldsm4(kbl, patB(sm32 + B_KVTL, LDA, g4 * 16, ks * 16, lane));
                mma_bf16(oacc[2 * g4], a4h, kbh);     mma_bf16(oacc[2 * g4], a4h, kbl);
                mma_bf16(oacc[2 * g4], a4l, kbh);
                mma_bf16(oacc[2 * g4 + 1], a4h, kbh + 2); mma_bf16(oacc[2 * g4 + 1], a4h, kbl + 2);
                mma_bf16(oacc[2 * g4 + 1], a4l, kbh + 2);
            }
        }

        if (sc + 1 < CPS_B) ld_tile128(qbase + (sc + 1) * 128, tid, qreg);

        // ---- transpose bounce: oacc(n,e2) -> outbuf[e2][n] ----
        float* ob = (float*)(sm + B_OUT);
        #pragma unroll
        for (int g = 0; g < 8; g++) {
            int col = g * 8 + 2 * (lane & 3);
            int row = n0w + (lane >> 2);
            ob[col * LDO + row]           = oacc[g][0];
            ob[(col + 1) * LDO + row]     = oacc[g][1];
            ob[col * LDO + row + 8]       = oacc[g][2];
            ob[(col + 1) * LDO + row + 8] = oacc[g][3];
        }
        __syncthreads();

        // ---- coalesced fp32 stores ----
        float* og = obase + sc * 128;
        #pragma unroll
        for (int i = 0; i < 8; i++) {
            int idx4 = tid + i * 256;
            int r = idx4 >> 5, c4 = (idx4 & 31) * 4;
            float4 val = *(const float4*)(ob + r * LDO + c4);
            *(float4*)(og + (size_t)r * N + c4) = val;
        }
        __syncthreads();
    }
}

extern "C" void kernel_launch(void* const* d_in, const int* in_sizes, int n_in,
                              void* d_out, int out_size) {
    const float* q  = (const float*)d_in[0];
    const float* k  = (const float*)d_in[1];
    const float* v  = (const float*)d_in[2];
    const float* Wf = (const float*)d_in[3];
    const float* bf = (const float*)d_in[4];
    float* out = (float*)d_out;

    cudaFuncSetAttribute(kernelA, cudaFuncAttributeMaxDynamicSharedMemorySize, A_SMEM);
    cudaFuncSetAttribute(kernelB, cudaFuncAttributeMaxDynamicSharedMemorySize, B_SMEM);

    kernelA<<<dim3(SPLITS, BH), 256, A_SMEM>>>(k, v, Wf, bf);
    kernelR<<<BH, 256>>>();
    kernelB<<<dim3(SPLITS, BH), 256, B_SMEM>>>(q, Wf, bf, out);
}